// round 2
// baseline (speedup 1.0000x reference)
#include <cuda_runtime.h>

#define HN 4
#define C  64
#define H  256
#define W  448
#define HW (H*W)            // 114688
#define NP (HN*HW)          // 458752 source pixels
#define CP 68               // padded channel count: 64 data + 1 metric + 3 pad (272B/pixel, 16B aligned)

// Channel-last accumulation scratch: [NP][CP] floats = 124.8 MB
__device__ float g_acc[(size_t)NP * CP];

__device__ __forceinline__ void red_add_v4(float* addr, float a, float b, float c, float d) {
    asm volatile("red.global.add.v4.f32 [%0], {%1,%2,%3,%4};"
                 :: "l"(addr), "f"(a), "f"(b), "f"(c), "f"(d) : "memory");
}

__global__ void zero_kernel() {
    size_t i = (size_t)blockIdx.x * blockDim.x + threadIdx.x;
    size_t n4 = (size_t)NP * CP / 4;
    float4* p = reinterpret_cast<float4*>(g_acc);
    if (i < n4) p[i] = make_float4(0.f, 0.f, 0.f, 0.f);
}

__global__ void splat_kernel(const float* __restrict__ inp,
                             const float* __restrict__ flow,
                             const float* __restrict__ metric) {
    int g = blockIdx.x * blockDim.x + threadIdx.x;
    if (g >= NP) return;
    int n   = g / HW;
    int pix = g - n * HW;
    int y   = pix / W;
    int x   = pix - y * W;

    float fx = (float)x + flow[(n * 2 + 0) * HW + pix];
    float fy = (float)y + flow[(n * 2 + 1) * HW + pix];
    float m  = __expf(metric[g]);

    float x0f = floorf(fx), y0f = floorf(fy);
    float ax = fx - x0f, ay = fy - y0f;
    int x0 = (int)x0f, y0 = (int)y0f;

    float wgt[4];
    wgt[0] = (1.f - ax) * (1.f - ay);
    wgt[1] = ax * (1.f - ay);
    wgt[2] = (1.f - ax) * ay;
    wgt[3] = ax * ay;

    int  bofs[4];
    bool val[4];
#pragma unroll
    for (int k = 0; k < 4; k++) {
        int xi = x0 + (k & 1);
        int yi = y0 + (k >> 1);
        val[k]  = (xi >= 0) && (xi < W) && (yi >= 0) && (yi < H);
        bofs[k] = (n * HW + yi * W + xi) * CP;
    }

    // metric channel (index 64): scalar red
#pragma unroll
    for (int k = 0; k < 4; k++)
        if (val[k]) atomicAdd(&g_acc[bofs[k] + 64], m * wgt[k]);

    const float* src = inp + (size_t)n * C * HW + pix;
#pragma unroll 4
    for (int c = 0; c < C; c += 4) {
        float v0 = src[(c + 0) * HW] * m;
        float v1 = src[(c + 1) * HW] * m;
        float v2 = src[(c + 2) * HW] * m;
        float v3 = src[(c + 3) * HW] * m;
#pragma unroll
        for (int k = 0; k < 4; k++) {
            if (val[k]) {
                red_add_v4(&g_acc[bofs[k] + c],
                           v0 * wgt[k], v1 * wgt[k], v2 * wgt[k], v3 * wgt[k]);
            }
        }
    }
}

// Normalize + NHWC->NCHW transpose. Block handles 32 consecutive pixels, 256 threads.
#define SP 69  // smem row stride (odd -> conflict-free)
__global__ void norm_kernel(float* __restrict__ out) {
    __shared__ float s[32 * SP];
    int t = threadIdx.x;
    size_t pixbase = (size_t)blockIdx.x * 32;   // global (n*HW + pix) base

    const float* src = g_acc + pixbase * CP;
    for (int i = t; i < 32 * CP; i += 256) {
        int p = i / CP;
        int c = i - p * CP;
        s[p * SP + c] = src[i];
    }
    __syncthreads();

    int p  = t & 31;    // lane -> pixel (coalesced writes)
    int c0 = t >> 5;    // warp -> channel phase
    size_t gp  = pixbase + p;
    int n   = (int)(gp / HW);
    int pix = (int)(gp - (size_t)n * HW);

    float norm = s[p * SP + 64];
    float inv  = (norm == 0.f) ? 1.f : 1.f / norm;

#pragma unroll
    for (int c = c0; c < C; c += 8) {
        out[((size_t)(n * C + c)) * HW + pix] = s[p * SP + c] * inv;
    }
}

extern "C" void kernel_launch(void* const* d_in, const int* in_sizes, int n_in,
                              void* d_out, int out_size) {
    const float* inp    = (const float*)d_in[0];   // (4,64,256,448)
    const float* flow   = (const float*)d_in[1];   // (4,2,256,448)
    const float* metric = (const float*)d_in[2];   // (4,1,256,448)
    float* out = (float*)d_out;

    {
        size_t n4 = (size_t)NP * CP / 4;
        int blocks = (int)((n4 + 255) / 256);
        zero_kernel<<<blocks, 256>>>();
    }
    {
        int blocks = (NP + 255) / 256;
        splat_kernel<<<blocks, 256>>>(inp, flow, metric);
    }
    {
        int blocks = NP / 32;
        norm_kernel<<<blocks, 256>>>(out);
    }
}

// round 3
// speedup vs baseline: 1.5747x; 1.5747x over previous
#include <cuda_runtime.h>

#define HN 4
#define C  64
#define H  256
#define W  448
#define HW (H*W)            // 114688
#define NP (HN*HW)          // 458752 source pixels
#define CP 68               // 64 data + 1 metric + 3 pad (272B record, 16B aligned)

// Channel-last accumulation scratch: [NP][CP] floats = 124.8 MB (~L2 sized)
__device__ float g_acc[(size_t)NP * CP];

__device__ __forceinline__ void red_add_v4(float* addr, float a, float b, float c, float d) {
    asm volatile("red.global.add.v4.f32 [%0], {%1,%2,%3,%4};"
                 :: "l"(addr), "f"(a), "f"(b), "f"(c), "f"(d) : "memory");
}

#define PX 64               // pixels per block
#define THREADS 256

// Warp-contiguous splat: warp = 2 pixels x 16 lanes (4 channels/lane).
// Each red.v4 instruction touches 2 contiguous 256B corner records (~5 lines)
// instead of 32 scattered lines.
__global__ __launch_bounds__(THREADS) void splat_kernel(
        const float* __restrict__ inp,
        const float* __restrict__ flow,
        const float* __restrict__ metric) {
    __shared__ float s_in[PX * 65];    // [pixel][channel], stride 65 (conflict-free)
    __shared__ float s_m[PX];
    __shared__ float s_w[4][PX];
    __shared__ int   s_bo[4][PX];

    int t  = threadIdx.x;
    int g0 = blockIdx.x * PX;          // global source index base (n*HW + pix)
    int n  = g0 / HW;                  // HW % PX == 0 -> block never straddles n
    int pixbase = g0 - n * HW;

    if (t < PX) {
        int pix = pixbase + t;
        int y = pix / W, x = pix - y * W;
        float fx = (float)x + flow[(n * 2 + 0) * HW + pix];
        float fy = (float)y + flow[(n * 2 + 1) * HW + pix];
        float m  = __expf(metric[n * HW + pix]);
        s_m[t] = m;
        float x0f = floorf(fx), y0f = floorf(fy);
        float ax = fx - x0f, ay = fy - y0f;
        int x0 = (int)x0f, y0 = (int)y0f;
        float wk0 = (1.f - ax) * (1.f - ay);
        float wk1 = ax * (1.f - ay);
        float wk2 = (1.f - ax) * ay;
        float wk3 = ax * ay;
        float wks[4] = {wk0, wk1, wk2, wk3};
#pragma unroll
        for (int k = 0; k < 4; k++) {
            int xi = x0 + (k & 1);
            int yi = y0 + (k >> 1);
            bool v = (xi >= 0) && (xi < W) && (yi >= 0) && (yi < H);
            s_w[k][t]  = wks[k];
            s_bo[k][t] = v ? (n * HW + yi * W + xi) * CP : -1;
        }
    }
    __syncthreads();

    // Stage input, pre-scaled by metric. Coalesced global reads; stride-65
    // smem stores are bank-conflict-free.
    const float* src = inp + (size_t)n * C * HW + pixbase;
#pragma unroll
    for (int k = 0; k < (PX * C) / THREADS; k++) {
        int i = t + k * THREADS;       // i = c*64 + p
        int c = i >> 6;
        int p = i & 63;
        s_in[p * 65 + c] = src[(size_t)c * HW + p] * s_m[p];
    }
    __syncthreads();

    int lane = t & 31;
    int w    = t >> 5;
    int cg   = (lane & 15) * 4;        // channel group base
    int hi   = lane >> 4;              // which of the warp's 2 pixels
#pragma unroll
    for (int j = 0; j < 4; j++) {
        int p = j * 16 + w * 2 + hi;   // pixel index within block
        float b0 = s_in[p * 65 + cg + 0];
        float b1 = s_in[p * 65 + cg + 1];
        float b2 = s_in[p * 65 + cg + 2];
        float b3 = s_in[p * 65 + cg + 3];
        float m  = s_m[p];
#pragma unroll
        for (int k = 0; k < 4; k++) {
            int bo   = s_bo[k][p];
            float wk = s_w[k][p];
            if (bo >= 0) {
                red_add_v4(&g_acc[bo + cg], b0 * wk, b1 * wk, b2 * wk, b3 * wk);
                if (cg == 0)  // metric slot (+ pads, which stay 0)
                    red_add_v4(&g_acc[bo + 64], m * wk, 0.f, 0.f, 0.f);
            }
        }
    }
}

// Normalize + NHWC->NCHW transpose, and zero the scratch region behind us
// (fused zero: every invocation leaves g_acc zeroed; initial state is zeroed
// by CUDA module load).
#define SP 69
__global__ __launch_bounds__(256) void norm_kernel(float* __restrict__ out) {
    __shared__ float s[32 * SP];
    int t = threadIdx.x;
    size_t pixbase = (size_t)blockIdx.x * 32;

    float* src = g_acc + pixbase * CP;
    for (int i = t; i < 32 * CP; i += 256) {
        int p = i / CP;
        int c = i - p * CP;
        s[p * SP + c] = src[i];
    }
    __syncthreads();

    // zero our region (16B-aligned, 544 float4s)
    float4* z = reinterpret_cast<float4*>(src);
    for (int i = t; i < (32 * CP) / 4; i += 256)
        z[i] = make_float4(0.f, 0.f, 0.f, 0.f);

    int p  = t & 31;
    int c0 = t >> 5;
    size_t gp = pixbase + p;
    int n   = (int)(gp / HW);
    int pix = (int)(gp - (size_t)n * HW);

    float norm = s[p * SP + 64];
    float inv  = (norm == 0.f) ? 1.f : 1.f / norm;

#pragma unroll
    for (int c = c0; c < C; c += 8)
        out[((size_t)(n * C + c)) * HW + pix] = s[p * SP + c] * inv;
}

extern "C" void kernel_launch(void* const* d_in, const int* in_sizes, int n_in,
                              void* d_out, int out_size) {
    const float* inp    = (const float*)d_in[0];   // (4,64,256,448)
    const float* flow   = (const float*)d_in[1];   // (4,2,256,448)
    const float* metric = (const float*)d_in[2];   // (4,1,256,448)
    float* out = (float*)d_out;

    splat_kernel<<<NP / PX, THREADS>>>(inp, flow, metric);
    norm_kernel<<<NP / 32, 256>>>(out);
}

// round 5
// speedup vs baseline: 2.0569x; 1.3062x over previous
#include <cuda_runtime.h>

#define HN 4
#define C  64
#define H  256
#define W  448
#define HW (H*W)            // 114688
#define NP (HN*HW)          // 458752 source pixels

// Channel-last accumulation scratch: [NP][64] floats = 117 MB, 256B records
__device__ __align__(256) float g_acc[(size_t)NP * C];
__device__ __align__(16)  float g_met[NP];

__device__ __forceinline__ void red_add_v4(float* addr, float a, float b, float c, float d) {
    asm volatile("red.global.add.v4.f32 [%0], {%1,%2,%3,%4};"
                 :: "l"(addr), "f"(a), "f"(b), "f"(c), "f"(d) : "memory");
}

#define PX 64
#define THREADS 256
#define SI 65    // s_in stride (scalar, conflict-free)

// Splat: warp instruction = 1 pixel x 2 x-adjacent corners (contiguous 512B span).
__global__ __launch_bounds__(THREADS) void splat_kernel(
        const float* __restrict__ inp,
        const float* __restrict__ flow,
        const float* __restrict__ metric) {
    __shared__ float s_in[PX * SI];   // [pixel][channel] pre-scaled by exp(metric)
    __shared__ float s_m[PX];
    __shared__ float s_w[4][PX];
    __shared__ int   s_bo[4][PX];     // record offset *C, or -1 if invalid

    int t  = threadIdx.x;
    int g0 = blockIdx.x * PX;
    int n  = g0 / HW;                 // HW % PX == 0
    int pixbase = g0 - n * HW;

    if (t < PX) {
        int pix = pixbase + t;
        int y = pix / W, x = pix - y * W;
        float fx = (float)x + flow[(n * 2 + 0) * HW + pix];
        float fy = (float)y + flow[(n * 2 + 1) * HW + pix];
        float m  = __expf(metric[n * HW + pix]);
        s_m[t] = m;
        float x0f = floorf(fx), y0f = floorf(fy);
        float ax = fx - x0f, ay = fy - y0f;
        int x0 = (int)x0f, y0 = (int)y0f;
        float wks[4] = {(1.f - ax) * (1.f - ay), ax * (1.f - ay),
                        (1.f - ax) * ay,          ax * ay};
#pragma unroll
        for (int k = 0; k < 4; k++) {
            int xi = x0 + (k & 1);
            int yi = y0 + (k >> 1);
            bool v = (xi >= 0) && (xi < W) && (yi >= 0) && (yi < H);
            s_w[k][t]  = wks[k];
            s_bo[k][t] = v ? (n * HW + yi * W + xi) * C : -1;
        }
    }
    __syncthreads();

    // Stage input via float4 loads, pre-scaled by metric.
    {
        const float* src = inp + (size_t)n * C * HW + pixbase;
        int p4 = (t & 15) * 4;
#pragma unroll
        for (int k = 0; k < 4; k++) {
            int c = (t >> 4) + k * 16;
            float4 v = *reinterpret_cast<const float4*>(&src[(size_t)c * HW + p4]);
            s_in[(p4 + 0) * SI + c] = v.x * s_m[p4 + 0];
            s_in[(p4 + 1) * SI + c] = v.y * s_m[p4 + 1];
            s_in[(p4 + 2) * SI + c] = v.z * s_m[p4 + 2];
            s_in[(p4 + 3) * SI + c] = v.w * s_m[p4 + 3];
        }
    }
    __syncthreads();

    int lane = t & 31;
    int w    = t >> 5;
    int side = lane >> 4;             // 0 -> x0 corner, 1 -> x1 corner
    int cg   = (lane & 15) * 4;       // channel group
#pragma unroll
    for (int j = 0; j < 8; j++) {
        int p = w * 8 + j;            // warp owns 8 consecutive pixels
        float b0 = s_in[p * SI + cg + 0];
        float b1 = s_in[p * SI + cg + 1];
        float b2 = s_in[p * SI + cg + 2];
        float b3 = s_in[p * SI + cg + 3];
#pragma unroll
        for (int row = 0; row < 2; row++) {
            int k    = row * 2 + side;
            int bo   = s_bo[k][p];
            float wk = s_w[k][p];
            if (bo >= 0)
                red_add_v4(&g_acc[bo + cg], b0 * wk, b1 * wk, b2 * wk, b3 * wk);
        }
        if (lane < 4) {               // metric scatter: one lane per corner
            int bo = s_bo[lane][p];
            if (bo >= 0) atomicAdd(&g_met[bo >> 6], s_m[p] * s_w[lane][p]);
        }
    }
}

// Normalize + NHWC->NCHW transpose + fused scratch zeroing (leaves g_acc/g_met
// zeroed for the next replay; initial state is zero from module load).
#define SP 65
__global__ __launch_bounds__(256) void norm_kernel(float* __restrict__ out) {
    __shared__ float s[32 * SP];
    __shared__ float s_inv[32];
    int t = threadIdx.x;
    size_t pixbase = (size_t)blockIdx.x * 32;

    float4* src4 = reinterpret_cast<float4*>(g_acc + pixbase * C);
#pragma unroll
    for (int k = 0; k < 2; k++) {
        int i = t + k * 256;          // i = p*16 + cq
        int p = i >> 4, cq = i & 15;
        float4 v = src4[i];
        s[p * SP + cq * 4 + 0] = v.x;
        s[p * SP + cq * 4 + 1] = v.y;
        s[p * SP + cq * 4 + 2] = v.z;
        s[p * SP + cq * 4 + 3] = v.w;
    }
    if (t < 32) {
        float nm = g_met[pixbase + t];
        s_inv[t] = (nm == 0.f) ? 1.f : 1.f / nm;
    }
    __syncthreads();

    // zero scratch behind us
#pragma unroll
    for (int k = 0; k < 2; k++)
        src4[t + k * 256] = make_float4(0.f, 0.f, 0.f, 0.f);
    if (t < 32) g_met[pixbase + t] = 0.f;

    int n   = (int)(pixbase / HW);    // HW % 32 == 0
    int pix = (int)(pixbase - (size_t)n * HW);

#pragma unroll
    for (int k = 0; k < 2; k++) {
        int idx = t + k * 256;        // idx = c*8 + (p4/4)
        int c   = idx >> 3;
        int p4  = (idx & 7) * 4;
        float4 o;
        o.x = s[(p4 + 0) * SP + c] * s_inv[p4 + 0];
        o.y = s[(p4 + 1) * SP + c] * s_inv[p4 + 1];
        o.z = s[(p4 + 2) * SP + c] * s_inv[p4 + 2];
        o.w = s[(p4 + 3) * SP + c] * s_inv[p4 + 3];
        *reinterpret_cast<float4*>(&out[((size_t)(n * C + c)) * HW + pix + p4]) = o;
    }
}

extern "C" void kernel_launch(void* const* d_in, const int* in_sizes, int n_in,
                              void* d_out, int out_size) {
    const float* inp    = (const float*)d_in[0];   // (4,64,256,448)
    const float* flow   = (const float*)d_in[1];   // (4,2,256,448)
    const float* metric = (const float*)d_in[2];   // (4,1,256,448)
    float* out = (float*)d_out;

    splat_kernel<<<NP / PX, THREADS>>>(inp, flow, metric);
    norm_kernel<<<NP / 32, 256>>>(out);
}

// round 10
// speedup vs baseline: 2.0616x; 1.0023x over previous
#include <cuda_runtime.h>

#define HN 4
#define C  64
#define H  256
#define W  448
#define HW (H*W)            // 114688
#define NP (HN*HW)          // 458752 source pixels

// Channel-last accumulation scratch: [NP][64] floats = 117 MB, 256B records
__device__ __align__(256) float g_acc[(size_t)NP * C];
__device__ __align__(16)  float g_met[NP];

__device__ __forceinline__ void red_add_v4(float* addr, float a, float b, float c, float d) {
    asm volatile("red.global.add.v4.f32 [%0], {%1,%2,%3,%4};"
                 :: "l"(addr), "f"(a), "f"(b), "f"(c), "f"(d) : "memory");
}

// 256-bit streaming load (read-once): evict-first in L2.
__device__ __forceinline__ void ldg_stream8(const float* p, float* r) {
    asm volatile("ld.global.nc.L2::evict_first.v8.b32 {%0,%1,%2,%3,%4,%5,%6,%7}, [%8];"
                 : "=f"(r[0]), "=f"(r[1]), "=f"(r[2]), "=f"(r[3]),
                   "=f"(r[4]), "=f"(r[5]), "=f"(r[6]), "=f"(r[7]) : "l"(p));
}
// 256-bit streaming store (write-once): evict-first.
__device__ __forceinline__ void stg_stream8(float* p, const float* r) {
    asm volatile("st.global.L2::evict_first.v8.b32 [%0], {%1,%2,%3,%4,%5,%6,%7,%8};"
                 :: "l"(p), "f"(r[0]), "f"(r[1]), "f"(r[2]), "f"(r[3]),
                    "f"(r[4]), "f"(r[5]), "f"(r[6]), "f"(r[7]) : "memory");
}
// 256-bit scratch access: evict-last (protect L2 residency across kernels/replays).
__device__ __forceinline__ void ldg_keep8(const float* p, float* r) {
    asm volatile("ld.global.L2::evict_last.v8.b32 {%0,%1,%2,%3,%4,%5,%6,%7}, [%8];"
                 : "=f"(r[0]), "=f"(r[1]), "=f"(r[2]), "=f"(r[3]),
                   "=f"(r[4]), "=f"(r[5]), "=f"(r[6]), "=f"(r[7]) : "l"(p));
}
__device__ __forceinline__ void stg_keep8_zero(float* p) {
    asm volatile("st.global.L2::evict_last.v8.b32 [%0], {%1,%1,%1,%1,%1,%1,%1,%1};"
                 :: "l"(p), "f"(0.f) : "memory");
}

#define PX 64
#define THREADS 256
#define SI 65    // s_in stride (scalar, conflict-free)

// Splat: warp instruction = 1 pixel x 2 x-adjacent corners (contiguous 512B span).
__global__ __launch_bounds__(THREADS) void splat_kernel(
        const float* __restrict__ inp,
        const float* __restrict__ flow,
        const float* __restrict__ metric) {
    __shared__ float s_in[PX * SI];   // [pixel][channel] pre-scaled by exp(metric)
    __shared__ float s_m[PX];
    __shared__ float s_w[4][PX];
    __shared__ int   s_bo[4][PX];     // record offset *C, or -1 if invalid

    int t  = threadIdx.x;
    int g0 = blockIdx.x * PX;
    int n  = g0 / HW;                 // HW % PX == 0
    int pixbase = g0 - n * HW;

    if (t < PX) {
        int pix = pixbase + t;
        int y = pix / W, x = pix - y * W;
        float fx = (float)x + flow[(n * 2 + 0) * HW + pix];
        float fy = (float)y + flow[(n * 2 + 1) * HW + pix];
        float m  = __expf(metric[n * HW + pix]);
        s_m[t] = m;
        float x0f = floorf(fx), y0f = floorf(fy);
        float ax = fx - x0f, ay = fy - y0f;
        int x0 = (int)x0f, y0 = (int)y0f;
        float wks[4] = {(1.f - ax) * (1.f - ay), ax * (1.f - ay),
                        (1.f - ax) * ay,          ax * ay};
#pragma unroll
        for (int k = 0; k < 4; k++) {
            int xi = x0 + (k & 1);
            int yi = y0 + (k >> 1);
            bool v = (xi >= 0) && (xi < W) && (yi >= 0) && (yi < H);
            s_w[k][t]  = wks[k];
            s_bo[k][t] = v ? (n * HW + yi * W + xi) * C : -1;
        }
    }
    __syncthreads();

    // Stage input via 256-bit streaming loads, pre-scaled by metric.
    {
        const float* src = inp + (size_t)n * C * HW + pixbase;
#pragma unroll
        for (int k = 0; k < 2; k++) {
            int i  = t + k * THREADS;     // i = c*8 + pg  (512 total)
            int c  = i >> 3;
            int p8 = (i & 7) * 8;
            float v[8];
            ldg_stream8(&src[(size_t)c * HW + p8], v);
#pragma unroll
            for (int j = 0; j < 8; j++)
                s_in[(p8 + j) * SI + c] = v[j] * s_m[p8 + j];
        }
    }
    __syncthreads();

    int lane = t & 31;
    int w    = t >> 5;
    int side = lane >> 4;             // 0 -> x0 corner, 1 -> x1 corner
    int cg   = (lane & 15) * 4;       // channel group
#pragma unroll
    for (int j = 0; j < 8; j++) {
        int p = w * 8 + j;            // warp owns 8 consecutive pixels
        float b0 = s_in[p * SI + cg + 0];
        float b1 = s_in[p * SI + cg + 1];
        float b2 = s_in[p * SI + cg + 2];
        float b3 = s_in[p * SI + cg + 3];
#pragma unroll
        for (int row = 0; row < 2; row++) {
            int k    = row * 2 + side;
            int bo   = s_bo[k][p];
            float wk = s_w[k][p];
            if (bo >= 0)
                red_add_v4(&g_acc[bo + cg], b0 * wk, b1 * wk, b2 * wk, b3 * wk);
        }
        if (lane < 4) {               // metric scatter: one lane per corner
            int bo = s_bo[lane][p];
            if (bo >= 0) atomicAdd(&g_met[bo >> 6], s_m[p] * s_w[lane][p]);
        }
    }
}

// Normalize + NHWC->NCHW transpose + fused scratch zeroing (leaves g_acc/g_met
// zeroed for the next replay; initial state is zero from module load).
#define SP 65
__global__ __launch_bounds__(256) void norm_kernel(float* __restrict__ out) {
    __shared__ float s[32 * SP];
    __shared__ float s_inv[32];
    int t = threadIdx.x;
    size_t pixbase = (size_t)blockIdx.x * 32;

    float* src = g_acc + pixbase * C;     // 8 KB contiguous = 256 x 32B
    {
        int p  = t >> 3;                  // pixel 0..31
        int c0 = (t & 7) * 8;             // channel base
        float v[8];
        ldg_keep8(&src[t * 8], v);        // t*8 = p*64 + c0
#pragma unroll
        for (int j = 0; j < 8; j++)
            s[p * SP + c0 + j] = v[j];
    }
    if (t < 32) {
        float nm = g_met[pixbase + t];
        s_inv[t] = (nm == 0.f) ? 1.f : 1.f / nm;
    }
    __syncthreads();

    // zero scratch behind us, keeping the lines L2-resident for next replay
    stg_keep8_zero(&src[t * 8]);
    if (t < 32) g_met[pixbase + t] = 0.f;

    int n   = (int)(pixbase / HW);        // HW % 32 == 0
    int pix = (int)(pixbase - (size_t)n * HW);

    {
        int c  = t >> 2;                  // channel 0..63
        int p8 = (t & 3) * 8;             // pixel group base
        float o[8];
#pragma unroll
        for (int j = 0; j < 8; j++)       // bank = (p8+j)*65 + c mod 32: conflict-free
            o[j] = s[(p8 + j) * SP + c] * s_inv[p8 + j];
        stg_stream8(&out[((size_t)(n * C + c)) * HW + pix + p8], o);
    }
}

extern "C" void kernel_launch(void* const* d_in, const int* in_sizes, int n_in,
                              void* d_out, int out_size) {
    const float* inp    = (const float*)d_in[0];   // (4,64,256,448)
    const float* flow   = (const float*)d_in[1];   // (4,2,256,448)
    const float* metric = (const float*)d_in[2];   // (4,1,256,448)
    float* out = (float*)d_out;

    splat_kernel<<<NP / PX, THREADS>>>(inp, flow, metric);
    norm_kernel<<<NP / 32, 256>>>(out);
}

// round 14
// speedup vs baseline: 2.6331x; 1.2772x over previous
#include <cuda_runtime.h>
#include <cuda_fp16.h>

#define HN 4
#define C  64
#define H  256
#define W  448
#define HW (H*W)            // 114688
#define NP (HN*HW)          // 458752 source pixels

// Channel-last fp16 accumulation scratch: [NP][64] halves = 58.7 MB, 128B records
__device__ __align__(128) __half g_acc[(size_t)NP * C];
__device__ __align__(16)  float  g_met[NP];   // metric norm stays fp32

__device__ __forceinline__ unsigned f22h2(float a, float b) {
    __half2 h = __floats2half2_rn(a, b);
    return *reinterpret_cast<unsigned*>(&h);
}

// 16B fp16x2 vector reduction: 8 channels per lane, one instruction.
__device__ __forceinline__ void red_add_v4h2(__half* addr, unsigned h0, unsigned h1,
                                             unsigned h2, unsigned h3) {
    asm volatile("red.global.add.noftz.v4.f16x2 [%0], {%1,%2,%3,%4};"
                 :: "l"(addr), "r"(h0), "r"(h1), "r"(h2), "r"(h3) : "memory");
}

// 256-bit streaming load/store (evict-first) and scratch zero (evict-last).
__device__ __forceinline__ void ldg_stream8(const float* p, float* r) {
    asm volatile("ld.global.nc.L2::evict_first.v8.b32 {%0,%1,%2,%3,%4,%5,%6,%7}, [%8];"
                 : "=f"(r[0]), "=f"(r[1]), "=f"(r[2]), "=f"(r[3]),
                   "=f"(r[4]), "=f"(r[5]), "=f"(r[6]), "=f"(r[7]) : "l"(p));
}
__device__ __forceinline__ void stg_stream8(float* p, const float* r) {
    asm volatile("st.global.L2::evict_first.v8.b32 [%0], {%1,%2,%3,%4,%5,%6,%7,%8};"
                 :: "l"(p), "f"(r[0]), "f"(r[1]), "f"(r[2]), "f"(r[3]),
                    "f"(r[4]), "f"(r[5]), "f"(r[6]), "f"(r[7]) : "memory");
}
__device__ __forceinline__ void ldg_keep8u(const __half* p, unsigned* r) {
    asm volatile("ld.global.L2::evict_last.v8.b32 {%0,%1,%2,%3,%4,%5,%6,%7}, [%8];"
                 : "=r"(r[0]), "=r"(r[1]), "=r"(r[2]), "=r"(r[3]),
                   "=r"(r[4]), "=r"(r[5]), "=r"(r[6]), "=r"(r[7]) : "l"(p));
}
__device__ __forceinline__ void stg_keep8_zero(__half* p) {
    asm volatile("st.global.L2::evict_last.v8.b32 [%0], {%1,%1,%1,%1,%1,%1,%1,%1};"
                 :: "l"(p), "r"(0u) : "memory");
}

#define PX 64
#define THREADS 256
#define SI 65    // s_in stride (scalar, conflict-free-ish)

// Splat: one warp instruction = 1 pixel x 4 corners x 64 channels (fp16x2 v4 red).
__global__ __launch_bounds__(THREADS) void splat_kernel(
        const float* __restrict__ inp,
        const float* __restrict__ flow,
        const float* __restrict__ metric) {
    __shared__ float s_in[PX * SI];   // [pixel][channel] pre-scaled by exp(metric)
    __shared__ float s_m[PX];
    __shared__ float s_w[4][PX];
    __shared__ int   s_r[4][PX];      // dest record index (n*HW+y*W+x), or -1

    int t  = threadIdx.x;
    int g0 = blockIdx.x * PX;
    int n  = g0 / HW;                 // HW % PX == 0
    int pixbase = g0 - n * HW;

    if (t < PX) {
        int pix = pixbase + t;
        int y = pix / W, x = pix - y * W;
        float fx = (float)x + flow[(n * 2 + 0) * HW + pix];
        float fy = (float)y + flow[(n * 2 + 1) * HW + pix];
        float m  = __expf(metric[n * HW + pix]);
        s_m[t] = m;
        float x0f = floorf(fx), y0f = floorf(fy);
        float ax = fx - x0f, ay = fy - y0f;
        int x0 = (int)x0f, y0 = (int)y0f;
        float wks[4] = {(1.f - ax) * (1.f - ay), ax * (1.f - ay),
                        (1.f - ax) * ay,          ax * ay};
#pragma unroll
        for (int k = 0; k < 4; k++) {
            int xi = x0 + (k & 1);
            int yi = y0 + (k >> 1);
            bool v = (xi >= 0) && (xi < W) && (yi >= 0) && (yi < H);
            s_w[k][t] = wks[k];
            s_r[k][t] = v ? (n * HW + yi * W + xi) : -1;
        }
    }
    __syncthreads();

    // Stage input via 256-bit streaming loads, pre-scaled by metric.
    {
        const float* src = inp + (size_t)n * C * HW + pixbase;
#pragma unroll
        for (int k = 0; k < 2; k++) {
            int i  = t + k * THREADS;     // i = c*8 + pg  (512 total)
            int c  = i >> 3;
            int p8 = (i & 7) * 8;
            float v[8];
            ldg_stream8(&src[(size_t)c * HW + p8], v);
#pragma unroll
            for (int j = 0; j < 8; j++)
                s_in[(p8 + j) * SI + c] = v[j] * s_m[p8 + j];
        }
    }
    __syncthreads();

    int lane   = t & 31;
    int w      = t >> 5;
    int corner = lane >> 3;           // 0..3 : 8 lanes per corner
    int cb     = (lane & 7) * 8;      // channel base: 8 channels per lane
#pragma unroll
    for (int j = 0; j < 8; j++) {
        int p = w * 8 + j;            // warp owns 8 consecutive pixels
        int   r  = s_r[corner][p];
        float wk = s_w[corner][p];
        if (r >= 0) {
            const float* sp = &s_in[p * SI + cb];
            unsigned h0 = f22h2(sp[0] * wk, sp[1] * wk);
            unsigned h1 = f22h2(sp[2] * wk, sp[3] * wk);
            unsigned h2 = f22h2(sp[4] * wk, sp[5] * wk);
            unsigned h3 = f22h2(sp[6] * wk, sp[7] * wk);
            red_add_v4h2(g_acc + (size_t)r * C + cb, h0, h1, h2, h3);
        }
        if (lane < 4) {               // metric scatter: one lane per corner (fp32)
            int rm = s_r[lane][p];
            if (rm >= 0) atomicAdd(&g_met[rm], s_m[p] * s_w[lane][p]);
        }
    }
}

// Normalize + NHWC(fp16)->NCHW(fp32) transpose + fused scratch zeroing.
#define SP 65
__global__ __launch_bounds__(256) void norm_kernel(float* __restrict__ out) {
    __shared__ float s[32 * SP];
    __shared__ float s_inv[32];
    int t = threadIdx.x;
    size_t pixbase = (size_t)blockIdx.x * 32;

    __half* src = g_acc + pixbase * C;    // 4 KB contiguous (32 px x 128B)
    if (t < 128) {
        int p  = t >> 2;                  // pixel 0..31
        int c0 = (t & 3) * 16;            // 16 halves per 32B load
        unsigned v[8];
        ldg_keep8u(&src[(size_t)t * 16], v);
#pragma unroll
        for (int j = 0; j < 8; j++) {
            float2 f = __half22float2(*reinterpret_cast<__half2*>(&v[j]));
            s[p * SP + c0 + j * 2 + 0] = f.x;
            s[p * SP + c0 + j * 2 + 1] = f.y;
        }
    }
    if (t >= 128 && t < 160) {
        float nm = g_met[pixbase + (t - 128)];
        s_inv[t - 128] = (nm == 0.f) ? 1.f : 1.f / nm;
    }
    __syncthreads();

    // zero scratch behind us (leaves state ready for next replay)
    if (t < 128) stg_keep8_zero(&src[(size_t)t * 16]);
    if (t >= 128 && t < 160) g_met[pixbase + (t - 128)] = 0.f;

    int n   = (int)(pixbase / HW);        // HW % 32 == 0
    int pix = (int)(pixbase - (size_t)n * HW);

    {
        int c  = t >> 2;                  // channel 0..63
        int p8 = (t & 3) * 8;             // pixel group base
        float o[8];
#pragma unroll
        for (int j = 0; j < 8; j++)
            o[j] = s[(p8 + j) * SP + c] * s_inv[p8 + j];
        stg_stream8(&out[((size_t)(n * C + c)) * HW + pix + p8], o);
    }
}

extern "C" void kernel_launch(void* const* d_in, const int* in_sizes, int n_in,
                              void* d_out, int out_size) {
    const float* inp    = (const float*)d_in[0];   // (4,64,256,448)
    const float* flow   = (const float*)d_in[1];   // (4,2,256,448)
    const float* metric = (const float*)d_in[2];   // (4,1,256,448)
    float* out = (float*)d_out;

    splat_kernel<<<NP / PX, THREADS>>>(inp, flow, metric);
    norm_kernel<<<NP / 32, 256>>>(out);
}

// round 15
// speedup vs baseline: 2.6686x; 1.0135x over previous
#include <cuda_runtime.h>
#include <cuda_fp16.h>

#define HN 4
#define C  64
#define H  256
#define W  448
#define HW (H*W)            // 114688
#define NP (HN*HW)          // 458752 source pixels

// Channel-last fp16 accumulation scratch: [NP][64] halves = 58.7 MB, 128B records
__device__ __align__(128) __half g_acc[(size_t)NP * C];
__device__ __align__(16)  float  g_met[NP];   // metric norm stays fp32

__device__ __forceinline__ unsigned f22h2(float a, float b) {
    __half2 h = __floats2half2_rn(a, b);
    return *reinterpret_cast<unsigned*>(&h);
}

// 16B fp16x2 vector reduction: 8 channels per lane, one instruction.
__device__ __forceinline__ void red_add_v4h2(__half* addr, unsigned h0, unsigned h1,
                                             unsigned h2, unsigned h3) {
    asm volatile("red.global.add.noftz.v4.f16x2 [%0], {%1,%2,%3,%4};"
                 :: "l"(addr), "r"(h0), "r"(h1), "r"(h2), "r"(h3) : "memory");
}

// 256-bit streaming load/store (evict-first) and scratch access (evict-last).
__device__ __forceinline__ void ldg_stream8(const float* p, float* r) {
    asm volatile("ld.global.nc.L2::evict_first.v8.b32 {%0,%1,%2,%3,%4,%5,%6,%7}, [%8];"
                 : "=f"(r[0]), "=f"(r[1]), "=f"(r[2]), "=f"(r[3]),
                   "=f"(r[4]), "=f"(r[5]), "=f"(r[6]), "=f"(r[7]) : "l"(p));
}
__device__ __forceinline__ void stg_stream8(float* p, const float* r) {
    asm volatile("st.global.L2::evict_first.v8.b32 [%0], {%1,%2,%3,%4,%5,%6,%7,%8};"
                 :: "l"(p), "f"(r[0]), "f"(r[1]), "f"(r[2]), "f"(r[3]),
                    "f"(r[4]), "f"(r[5]), "f"(r[6]), "f"(r[7]) : "memory");
}
__device__ __forceinline__ void ldg_keep8u(const __half* p, unsigned* r) {
    asm volatile("ld.global.L2::evict_last.v8.b32 {%0,%1,%2,%3,%4,%5,%6,%7}, [%8];"
                 : "=r"(r[0]), "=r"(r[1]), "=r"(r[2]), "=r"(r[3]),
                   "=r"(r[4]), "=r"(r[5]), "=r"(r[6]), "=r"(r[7]) : "l"(p));
}
__device__ __forceinline__ void stg_keep8_zero(__half* p) {
    asm volatile("st.global.L2::evict_last.v8.b32 [%0], {%1,%1,%1,%1,%1,%1,%1,%1};"
                 :: "l"(p), "r"(0u) : "memory");
}

#define PX 64
#define THREADS 256
#define SI 65    // s_in stride (scalar float, conflict-free)

// Splat: one warp instruction = 1 pixel x 4 corners x 64 channels (fp16x2 v4 red).
__global__ __launch_bounds__(THREADS) void splat_kernel(
        const float* __restrict__ inp,
        const float* __restrict__ flow,
        const float* __restrict__ metric) {
    __shared__ float s_in[PX * SI];   // [pixel][channel] pre-scaled by exp(metric)
    __shared__ float s_m[PX];
    __shared__ float s_w[4][PX];
    __shared__ int   s_r[4][PX];      // dest record index (n*HW+y*W+x), or -1

    int t  = threadIdx.x;
    int g0 = blockIdx.x * PX;
    int n  = g0 / HW;                 // HW % PX == 0
    int pixbase = g0 - n * HW;

    // Setup: all 256 threads — thread = (pixel, corner). Redundant flow/metric
    // loads across the 4 corner groups hit L1.
    {
        int pt  = t & 63;             // pixel within block
        int k   = t >> 6;             // corner 0..3
        int pix = pixbase + pt;
        int y = pix / W, x = pix - y * W;
        float fx = (float)x + flow[(n * 2 + 0) * HW + pix];
        float fy = (float)y + flow[(n * 2 + 1) * HW + pix];
        float m  = __expf(metric[n * HW + pix]);
        if (k == 0) s_m[pt] = m;
        float x0f = floorf(fx), y0f = floorf(fy);
        float ax = fx - x0f, ay = fy - y0f;
        float wx = (k & 1)  ? ax : (1.f - ax);
        float wy = (k >> 1) ? ay : (1.f - ay);
        int xi = (int)x0f + (k & 1);
        int yi = (int)y0f + (k >> 1);
        bool v = (xi >= 0) && (xi < W) && (yi >= 0) && (yi < H);
        s_w[k][pt] = wx * wy;
        s_r[k][pt] = v ? (n * HW + yi * W + xi) : -1;
    }
    __syncthreads();

    // Stage input via 256-bit streaming loads, pre-scaled by metric.
    {
        const float* src = inp + (size_t)n * C * HW + pixbase;
#pragma unroll
        for (int k = 0; k < 2; k++) {
            int i  = t + k * THREADS;     // i = c*8 + pg  (512 total)
            int c  = i >> 3;
            int p8 = (i & 7) * 8;
            float v[8];
            ldg_stream8(&src[(size_t)c * HW + p8], v);
#pragma unroll
            for (int j = 0; j < 8; j++)
                s_in[(p8 + j) * SI + c] = v[j] * s_m[p8 + j];
        }
    }
    __syncthreads();

    int lane   = t & 31;
    int w      = t >> 5;
    int corner = lane >> 3;           // 0..3 : 8 lanes per corner
    int cb     = (lane & 7) * 8;      // channel base: 8 channels per lane
#pragma unroll
    for (int j = 0; j < 8; j++) {
        int p = w * 8 + j;            // warp owns 8 consecutive pixels
        int   r  = s_r[corner][p];
        float wk = s_w[corner][p];
        if (r >= 0) {
            const float* sp = &s_in[p * SI + cb];
            unsigned h0 = f22h2(sp[0] * wk, sp[1] * wk);
            unsigned h1 = f22h2(sp[2] * wk, sp[3] * wk);
            unsigned h2 = f22h2(sp[4] * wk, sp[5] * wk);
            unsigned h3 = f22h2(sp[6] * wk, sp[7] * wk);
            red_add_v4h2(g_acc + (size_t)r * C + cb, h0, h1, h2, h3);
        }
        if (lane < 4) {               // metric scatter: one lane per corner (fp32)
            int rm = s_r[lane][p];
            if (rm >= 0) atomicAdd(&g_met[rm], s_m[p] * s_w[lane][p]);
        }
    }
}

// Normalize + NHWC(fp16)->NCHW(fp32) transpose + fused scratch zeroing.
// 64 px/block; smem holds raw half2 words. SU=33: store bank = p + 8*(t&3) + j
// (all distinct per warp); read addresses pairwise-broadcast, conflict-free.
#define NPX 64
#define SU  33
__global__ __launch_bounds__(256) void norm_kernel(float* __restrict__ out) {
    __shared__ unsigned s_u[NPX * SU];
    __shared__ float s_inv[NPX];
    int t = threadIdx.x;
    size_t pixbase = (size_t)blockIdx.x * NPX;

    __half* src = g_acc + pixbase * C;    // 8 KB contiguous (64 px x 128B)
    {
        int p  = t >> 2;                  // pixel 0..63
        int w0 = (t & 3) * 8;             // half2-word base within record
        unsigned v[8];
        ldg_keep8u(&src[(size_t)t * 16], v);
#pragma unroll
        for (int j = 0; j < 8; j++)
            s_u[p * SU + w0 + j] = v[j];
    }
    if (t < NPX) {
        float nm = g_met[pixbase + t];
        s_inv[t] = (nm == 0.f) ? 1.f : 1.f / nm;
    }
    __syncthreads();

    // zero scratch behind us (leaves state ready for next replay)
    stg_keep8_zero(&src[(size_t)t * 16]);
    if (t < NPX) g_met[pixbase + t] = 0.f;

    int n   = (int)(pixbase / HW);        // HW % 64 == 0
    int pix = (int)(pixbase - (size_t)n * HW);

    int c  = t >> 2;                      // channel 0..63
    int cw = c >> 1;                      // half2 word index
    int hi = c & 1;                       // low/high half
#pragma unroll
    for (int k = 0; k < 2; k++) {
        int p8 = ((t & 3) + k * 4) * 8;   // pixel group base 0..56
        float o[8];
#pragma unroll
        for (int j = 0; j < 8; j++) {
            unsigned u = s_u[(p8 + j) * SU + cw];
            __half2 h = *reinterpret_cast<__half2*>(&u);
            float f = hi ? __high2float(h) : __low2float(h);
            o[j] = f * s_inv[p8 + j];
        }
        stg_stream8(&out[((size_t)(n * C + c)) * HW + pix + p8], o);
    }
}

extern "C" void kernel_launch(void* const* d_in, const int* in_sizes, int n_in,
                              void* d_out, int out_size) {
    const float* inp    = (const float*)d_in[0];   // (4,64,256,448)
    const float* flow   = (const float*)d_in[1];   // (4,2,256,448)
    const float* metric = (const float*)d_in[2];   // (4,1,256,448)
    float* out = (float*)d_out;

    splat_kernel<<<NP / PX, THREADS>>>(inp, flow, metric);
    norm_kernel<<<NP / NPX, 256>>>(out);
}